// round 16
// baseline (speedup 1.0000x reference)
#include <cuda_runtime.h>
#include <cuda_bf16.h>
#include <cuda_fp16.h>
#include <cstdint>
#include <math.h>

#define CB   2
#define CS   4096
#define CD   1024
#define CH   16
#define CHD  64
#define CNB  64
#define CW   8
#define CM   (CB*CS)

// ---------------- scratch (device globals) ----------------------------------
__device__ float g_q[(size_t)CB*CH*CS*CHD];
__device__ float g_k[(size_t)CB*CH*CS*CHD];
__device__ float g_v[(size_t)CB*CH*CS*CHD];
__device__ float g_cos[CS*32];
__device__ float g_sin[CS*32];
__device__ __align__(256) __half g_Ah[(size_t)CM*CD];            // A hi (fp16)
__device__ __align__(256) __half g_Al[(size_t)CM*CD];            // A lo (fp16)
__device__ __align__(256) __half g_W16[(size_t)4*CD*CD];         // W fp16, [n][k]
__device__ __align__(256) __half g_q16[(size_t)CB*CH*CS*CHD];    // (bh,s,hd)
__device__ __align__(256) __half g_k16[(size_t)CB*CH*CS*CHD];    // (bh,s,hd)
__device__ __align__(256) __half g_vt [(size_t)CB*CH*CHD*CS];    // (bh,hd,s)

// ---------------- helpers ----------------------------------------------------
__device__ __forceinline__ uint32_t smem_u32(const void* p) {
    uint32_t a;
    asm("{ .reg .u64 t; cvta.to.shared.u64 t, %1; cvt.u32.u64 %0, t; }" : "=r"(a) : "l"(p));
    return a;
}
#define SWZ(o) ((o) ^ (((o) >> 3) & 0x70))

#define CP16(d, s) \
    asm volatile("cp.async.cg.shared.global [%0], [%1], 16;" :: "r"((uint32_t)(d)), "l"(s) : "memory")

__device__ __forceinline__ void ldsm4(uint32_t* r, uint32_t addr) {
    asm volatile("ldmatrix.sync.aligned.m8n8.x4.shared.b16 {%0,%1,%2,%3}, [%4];"
        : "=r"(r[0]), "=r"(r[1]), "=r"(r[2]), "=r"(r[3]) : "r"(addr));
}

__device__ __forceinline__ void mma_f16(float* c, const uint32_t* a, uint32_t b0, uint32_t b1) {
    asm volatile("mma.sync.aligned.m16n8k16.row.col.f32.f16.f16.f32 "
        "{%0,%1,%2,%3}, {%4,%5,%6,%7}, {%8,%9}, {%0,%1,%2,%3};"
        : "+f"(c[0]), "+f"(c[1]), "+f"(c[2]), "+f"(c[3])
        : "r"(a[0]), "r"(a[1]), "r"(a[2]), "r"(a[3]), "r"(b0), "r"(b1));
}

// exp2 without MUFU: magic-number round + deg-5 poly + exponent splice.
__device__ __forceinline__ float exp2p(float y) {
    y = fmaxf(y, -126.0f);
    float t = y + 12582912.0f;
    int   n = __float_as_int(t) - 0x4B400000;
    float f = y - (t - 12582912.0f);
    float p = 0.0013333558f;
    p = fmaf(p, f, 0.0096181291f);
    p = fmaf(p, f, 0.0555041087f);
    p = fmaf(p, f, 0.2402265069f);
    p = fmaf(p, f, 0.6931471806f);
    p = fmaf(p, f, 1.0f);
    return p * __int_as_float((n + 127) << 23);
}

__device__ __forceinline__ uint32_t pack_h2(float a, float b) {
    __half2 h = __floats2half2_rn(a, b);
    return *reinterpret_cast<uint32_t*>(&h);
}

// fp16 hi/lo split of one fp32 (A near-exact: residual ~2^-24)
__device__ __forceinline__ void split_f16(float x, __half& h, __half& l) {
    h = __float2half(x);
    l = __float2half(x - __half2float(h));
}

// ---------------- RoPE tables ------------------------------------------------
__global__ void rope_table_kernel() {
    int idx = blockIdx.x * blockDim.x + threadIdx.x;
    if (idx >= CS*32) return;
    int p = idx >> 5;
    int j = idx & 31;
    double expo = (double)(2*j) / 64.0;
    double freq = exp(-expo * log(10000.0));
    double ang  = (double)p * freq;
    g_cos[idx] = (float)cos(ang);
    g_sin[idx] = (float)sin(ang);
}

__global__ void rope_apply_kernel(const int* __restrict__ posids) {
    int idx = blockIdx.x * blockDim.x + threadIdx.x;
    int j  = idx & 31;
    int s  = (idx >> 5) & (CS - 1);
    int bh = idx >> 17;
    int b  = bh >> 4;
    int p  = posids[b*CS + s];
    float c  = g_cos[p*32 + j];
    float sn = g_sin[p*32 + j];
    size_t base = ((size_t)bh*CS + (size_t)s)*CHD + j;
    float q1 = g_q[base], q2 = g_q[base+32];
    g_q16[base]    = __float2half(q1*c - q2*sn);
    g_q16[base+32] = __float2half(q2*c + q1*sn);
    float k1 = g_k[base], k2 = g_k[base+32];
    g_k16[base]    = __float2half(k1*c - k2*sn);
    g_k16[base+32] = __float2half(k2*c + k1*sn);
}

// V: fp32 (bh,s,hd) -> fp16 transposed (bh,hd,s)
__global__ void conv_vt_kernel() {
    __shared__ float t[32][33];
    int bh = blockIdx.z;
    int s0 = blockIdx.x * 32;
    int h0 = blockIdx.y * 32;
    int tx = threadIdx.x, ty = threadIdx.y;   // 32 x 8
#pragma unroll
    for (int r = 0; r < 4; r++)
        t[ty + 8*r][tx] = g_v[((size_t)bh*CS + s0 + ty + 8*r)*CHD + h0 + tx];
    __syncthreads();
#pragma unroll
    for (int r = 0; r < 4; r++)
        g_vt[((size_t)bh*CHD + h0 + ty + 8*r)*CS + s0 + tx] = __float2half(t[tx][ty + 8*r]);
}

// ---------------- fp32 -> fp16 hi/lo split (row-major A) ---------------------
__global__ void conv_split_kernel(const float* __restrict__ src) {
    int i = blockIdx.x * blockDim.x + threadIdx.x;
    size_t base = (size_t)i * 4;
    float4 v = *(const float4*)(src + base);
    __half h0, h1, h2, h3, l0, l1, l2, l3;
    split_f16(v.x, h0, l0);
    split_f16(v.y, h1, l1);
    split_f16(v.z, h2, l2);
    split_f16(v.w, h3, l3);
    *(__half2*)(g_Ah + base)     = __halves2half2(h0, h1);
    *(__half2*)(g_Ah + base + 2) = __halves2half2(h2, h3);
    *(__half2*)(g_Al + base)     = __halves2half2(l0, l1);
    *(__half2*)(g_Al + base + 2) = __halves2half2(l2, l3);
}

// ---------------- weights: fp32 [k][n] -> fp16 transposed [n][k] -------------
__global__ void conv_w_kernel(const float* __restrict__ w0, const float* __restrict__ w1,
                              const float* __restrict__ w2, const float* __restrict__ w3) {
    __shared__ float t[32][33];
    int wz = blockIdx.z;
    const float* W = (wz == 0) ? w0 : (wz == 1) ? w1 : (wz == 2) ? w2 : w3;
    int n0 = blockIdx.x * 32, k0 = blockIdx.y * 32;
    int tx = threadIdx.x, ty = threadIdx.y;   // 32 x 8
#pragma unroll
    for (int r = 0; r < 4; r++) {
        int k = ty + r*8;
        t[k][tx] = W[(size_t)(k0 + k)*CD + n0 + tx];
    }
    __syncthreads();
    size_t off = (size_t)wz * CD * CD;
#pragma unroll
    for (int r = 0; r < 4; r++) {
        int nn = ty + r*8;
        g_W16[off + (size_t)(n0 + nn)*CD + k0 + tx] = __float2half(t[tx][nn]);
    }
}

// ---------------- split-fp16 GEMM via mma.sync (m16n8k16) --------------------
// C = (Ah + Al) @ B16. CTA 128x128, 512 thr, 16 warps (4m x 4n), warp 32x32.
// K-chunk 128 per stage (two 64-col sub-tiles) -> 8 stages, half the barriers.
#define G_TILE    16384                    /* one 128x64 fp16 tile             */
#define G_HALF    (3*G_TILE)               /* Ah,Al,B for one 64-col k-half    */
#define G_STAGE   (2*G_HALF)               /* 96KB: k-halves h=0,1             */
#define G_SMEM    (1024 + 2*G_STAGE)       /* 197632                           */

__device__ __forceinline__ void g_load_stage(uint32_t dat, int s, int m0, int n0, int tid,
                                             const __half* Bw) {
    uint32_t buf = dat + (uint32_t)(s & 1) * G_STAGE;
#pragma unroll
    for (int h = 0; h < 2; h++) {
        uint32_t hb = buf + h*G_HALF;
        int k0 = s*128 + h*64;
#pragma unroll
        for (int i = 0; i < 2; i++) {
            int cc  = tid + 512*i;
            int row = cc >> 3;
            int kc  = cc & 7;
            uint32_t d = SWZ(row*128 + kc*16);
            size_t ea = (size_t)(m0 + row)*CD + k0 + kc*8;
            size_t eb = (size_t)(n0 + row)*CD + k0 + kc*8;
            CP16(hb + d,             g_Ah + ea);
            CP16(hb + G_TILE + d,    g_Al + ea);
            CP16(hb + 2*G_TILE + d,  Bw + eb);
        }
    }
    asm volatile("cp.async.commit_group;" ::: "memory");
}

__global__ __launch_bounds__(512) void gemm_tc(int fused, float* __restrict__ outp) {
    extern __shared__ char smem_raw[];
    uint32_t sb_raw = smem_u32(smem_raw);
    uint32_t dat = (sb_raw + 1023u) & ~1023u;

    const int tid  = threadIdx.x;
    const int wid  = tid >> 5, lane = tid & 31;
    const int wm   = wid >> 2;
    const int wn   = wid & 3;
    const int m0   = blockIdx.x * 128;
    const int widx = fused ? (int)(blockIdx.y >> 3) : 3;
    const int n0   = fused ? (int)(blockIdx.y & 7) * 128 : (int)blockIdx.y * 128;
    const int mode = fused ? widx : 3;

    const __half* Bw = g_W16 + ((size_t)widx << 20);

    float acc[2][4][4];
#pragma unroll
    for (int mt = 0; mt < 2; mt++)
#pragma unroll
        for (int nt = 0; nt < 4; nt++)
#pragma unroll
            for (int e = 0; e < 4; e++) acc[mt][nt][e] = 0.f;

    const int g  = lane >> 3, r = lane & 7;
    const int arow = wm*32 + (g & 1)*8 + r;
    const int brow = wn*32 + (g & 1)*8 + r;
    const int kcol = (g >> 1) * 16;

    g_load_stage(dat, 0, m0, n0, tid, Bw);

    for (int s = 0; s < 8; s++) {
        if (s + 1 < 8) {
            g_load_stage(dat, s + 1, m0, n0, tid, Bw);
            asm volatile("cp.async.wait_group 1;" ::: "memory");
        } else {
            asm volatile("cp.async.wait_group 0;" ::: "memory");
        }
        __syncthreads();

        uint32_t buf = dat + (uint32_t)(s & 1) * G_STAGE;

#pragma unroll
        for (int h = 0; h < 2; h++) {
            uint32_t tAh = buf + h*G_HALF;
            uint32_t tAl = tAh + G_TILE;
            uint32_t tB  = tAh + 2*G_TILE;

#pragma unroll
            for (int ks = 0; ks < 4; ks++) {
                const int kb = ks*32 + kcol;
                uint32_t ah[2][4], al[2][4], bx[2][4];
#pragma unroll
                for (int mt = 0; mt < 2; mt++) {
                    ldsm4(ah[mt], tAh + SWZ((arow + mt*16)*128 + kb));
                    ldsm4(al[mt], tAl + SWZ((arow + mt*16)*128 + kb));
                }
#pragma unroll
                for (int ng = 0; ng < 2; ng++)
                    ldsm4(bx[ng], tB + SWZ((brow + ng*16)*128 + kb));
#pragma unroll
                for (int mt = 0; mt < 2; mt++)
#pragma unroll
                    for (int nt = 0; nt < 4; nt++)
                        mma_f16(acc[mt][nt], ah[mt], bx[nt>>1][nt&1], bx[nt>>1][(nt&1)+2]);
#pragma unroll
                for (int mt = 0; mt < 2; mt++)
#pragma unroll
                    for (int nt = 0; nt < 4; nt++)
                        mma_f16(acc[mt][nt], al[mt], bx[nt>>1][nt&1], bx[nt>>1][(nt&1)+2]);
            }
        }
        __syncthreads();
    }

    // epilogue
    const int gid = lane >> 2, tig = lane & 3;
    const int b_ = m0 >> 12;
    float* dst = (mode == 0) ? g_q : (mode == 1) ? g_k : g_v;
#pragma unroll
    for (int mt = 0; mt < 2; mt++) {
#pragma unroll
        for (int nt = 0; nt < 4; nt++) {
            int mrow = m0 + wm*32 + mt*16 + gid;
            int ncol = n0 + wn*32 + nt*8 + tig*2;
#pragma unroll
            for (int half = 0; half < 2; half++) {
                int m = mrow + half*8;
                float2 val = make_float2(acc[mt][nt][half*2], acc[mt][nt][half*2 + 1]);
                if (mode == 3) {
                    *(float2*)(outp + (size_t)m*CD + ncol) = val;
                } else {
                    int h  = ncol >> 6, hd = ncol & 63;
                    int s_ = m & (CS - 1);
                    *(float2*)(dst + (((size_t)(b_*CH + h))*CS + s_)*CHD + hd) = val;
                }
            }
        }
    }
}

// ---------------- fp16 tensor-core flash attention ---------------------------
// epilogue writes fp16 hi/lo A-operand for the output projection directly.
#define AT_TILE   8192
#define AT_SMEM   (1024 + 5*AT_TILE)

__device__ __forceinline__ void at_stage(uint32_t kbuf, const __half* ksrc,
                                         const __half* vtsrc, int tid) {
#pragma unroll
    for (int i = 0; i < 4; i++) {
        int cc  = tid + 128*i;
        int row = cc >> 3;
        int kc  = cc & 7;
        uint32_t d = SWZ(row*128 + kc*16);
        CP16(kbuf + d,           ksrc  + (size_t)row*CHD + kc*8);
        CP16(kbuf + AT_TILE + d, vtsrc + (size_t)row*CS  + kc*8);
    }
    asm volatile("cp.async.commit_group;" ::: "memory");
}

__global__ __launch_bounds__(128) void attn_tc_kernel() {
    extern __shared__ char sraw[];
    uint32_t dat = (smem_u32(sraw) + 1023u) & ~1023u;

    const int n   = blockIdx.x;
    const int bh  = blockIdx.y;
    const int tid = threadIdx.x;
    const int w   = tid >> 5, lane = tid & 31;
    const int g   = lane >> 3, r = lane & 7;
    const int gid = lane >> 2, tig = lane & 3;

    const __half* qsrc = g_q16 + ((size_t)bh*CS + (size_t)n*64)*CHD;
#pragma unroll
    for (int i = 0; i < 4; i++) {
        int cc = tid + 128*i;
        int row = cc >> 3;
        int kc  = cc & 7;
        CP16(dat + SWZ(row*128 + kc*16), qsrc + (size_t)row*CHD + kc*8);
    }
    asm volatile("cp.async.commit_group;" ::: "memory");

    const int kb0 = (n - (CW-1) < 0) ? 0 : n - (CW-1);
    const int nk  = n - kb0 + 1;
    const __half* kbase_g  = g_k16 + ((size_t)bh*CS)*CHD;
    const __half* vtbase_g = g_vt  + ((size_t)bh*CHD)*CS;

    at_stage(dat + AT_TILE, kbase_g + (size_t)kb0*64*CHD, vtbase_g + kb0*64, tid);

    float oacc[8][4];
#pragma unroll
    for (int nt = 0; nt < 8; nt++)
#pragma unroll
        for (int e = 0; e < 4; e++) oacc[nt][e] = 0.f;
    float m0 = -1e30f, m1 = -1e30f, l0 = 0.f, l1 = 0.f;
    uint32_t qf[4][4];

    const float SCL = 0.18033688011f;    // 0.125 * log2(e)
    const int ql0 = w*16 + gid, ql1 = ql0 + 8;

    for (int i = 0; i < nk; i++) {
        const int kb = kb0 + i;
        asm volatile("cp.async.wait_group 0;" ::: "memory");
        __syncthreads();

        if (i == 0) {
#pragma unroll
            for (int kc = 0; kc < 4; kc++)
                ldsm4(qf[kc], dat + SWZ((w*16 + (g&1)*8 + r)*128 + (g>>1)*16 + kc*32));
        }
        if (i + 1 < nk)
            at_stage(dat + AT_TILE + ((i+1)&1)*2*AT_TILE,
                     kbase_g + (size_t)(kb+1)*64*CHD, vtbase_g + (kb+1)*64, tid);

        const uint32_t kbuf = dat + AT_TILE + (i&1)*2*AT_TILE;
        const uint32_t vbuf = kbuf + AT_TILE;

        float sacc[8][4];
#pragma unroll
        for (int nt = 0; nt < 8; nt++)
#pragma unroll
            for (int e = 0; e < 4; e++) sacc[nt][e] = 0.f;

#pragma unroll
        for (int kc = 0; kc < 4; kc++) {
            uint32_t kf[4][4];
#pragma unroll
            for (int ng = 0; ng < 4; ng++)
                ldsm4(kf[ng], kbuf + SWZ((ng*16 + (g&1)*8 + r)*128 + (g>>1)*16 + kc*32));
#pragma unroll
            for (int nt = 0; nt < 8; nt++)
                mma_f16(sacc[nt], qf[kc], kf[nt>>1][nt&1], kf[nt>>1][(nt&1)+2]);
        }

#pragma unroll
        for (int nt = 0; nt < 8; nt++)
#pragma unroll
            for (int e = 0; e < 4; e++) sacc[nt][e] *= SCL;
        if (kb == n) {
#pragma unroll
            for (int nt = 0; nt < 8; nt++) {
                int c0 = nt*8 + 2*tig, c1 = c0 + 1;
                if (c0 > ql0) sacc[nt][0] = -1e30f;
                if (c1 > ql0) sacc[nt][1] = -1e30f;
                if (c0 > ql1) sacc[nt][2] = -1e30f;
                if (c1 > ql1) sacc[nt][3] = -1e30f;
            }
        }

        float mx0 = -1e30f, mx1 = -1e30f;
#pragma unroll
        for (int nt = 0; nt < 8; nt++) {
            mx0 = fmaxf(mx0, fmaxf(sacc[nt][0], sacc[nt][1]));
            mx1 = fmaxf(mx1, fmaxf(sacc[nt][2], sacc[nt][3]));
        }
        mx0 = fmaxf(mx0, __shfl_xor_sync(0xffffffffu, mx0, 1));
        mx0 = fmaxf(mx0, __shfl_xor_sync(0xffffffffu, mx0, 2));
        mx1 = fmaxf(mx1, __shfl_xor_sync(0xffffffffu, mx1, 1));
        mx1 = fmaxf(mx1, __shfl_xor_sync(0xffffffffu, mx1, 2));
        float mn0 = fmaxf(m0, mx0), mn1 = fmaxf(m1, mx1);
        float cr0 = exp2p(m0 - mn0), cr1 = exp2p(m1 - mn1);
        m0 = mn0; m1 = mn1;
        float rs0 = 0.f, rs1 = 0.f;
#pragma unroll
        for (int nt = 0; nt < 8; nt++) {
            sacc[nt][0] = exp2p(sacc[nt][0] - mn0);
            sacc[nt][1] = exp2p(sacc[nt][1] - mn0);
            sacc[nt][2] = exp2p(sacc[nt][2] - mn1);
            sacc[nt][3] = exp2p(sacc[nt][3] - mn1);
            rs0 += sacc[nt][0] + sacc[nt][1];
            rs1 += sacc[nt][2] + sacc[nt][3];
        }
        rs0 += __shfl_xor_sync(0xffffffffu, rs0, 1);
        rs0 += __shfl_xor_sync(0xffffffffu, rs0, 2);
        rs1 += __shfl_xor_sync(0xffffffffu, rs1, 1);
        rs1 += __shfl_xor_sync(0xffffffffu, rs1, 2);
        l0 = l0*cr0 + rs0;
        l1 = l1*cr1 + rs1;
#pragma unroll
        for (int nt = 0; nt < 8; nt++) {
            oacc[nt][0] *= cr0; oacc[nt][1] *= cr0;
            oacc[nt][2] *= cr1; oacc[nt][3] *= cr1;
        }

#pragma unroll
        for (int kc = 0; kc < 4; kc++) {
            uint32_t pf[4];
            pf[0] = pack_h2(sacc[2*kc][0],   sacc[2*kc][1]);
            pf[1] = pack_h2(sacc[2*kc][2],   sacc[2*kc][3]);
            pf[2] = pack_h2(sacc[2*kc+1][0], sacc[2*kc+1][1]);
            pf[3] = pack_h2(sacc[2*kc+1][2], sacc[2*kc+1][3]);
            uint32_t vf[4][4];
#pragma unroll
            for (int ng = 0; ng < 4; ng++)
                ldsm4(vf[ng], vbuf + SWZ((ng*16 + (g&1)*8 + r)*128 + (g>>1)*16 + kc*32));
#pragma unroll
            for (int nt = 0; nt < 8; nt++)
                mma_f16(oacc[nt], pf, vf[nt>>1][nt&1], vf[nt>>1][(nt&1)+2]);
        }
        __syncthreads();
    }

    // ---- epilogue: normalize, split to fp16 hi/lo into g_Ah/g_Al ------------
    const float inv0 = 1.0f / l0, inv1 = 1.0f / l1;
    const int b = bh >> 4, h = bh & 15;
    const int srow = n*64 + w*16 + gid;
#pragma unroll
    for (int nt = 0; nt < 8; nt++) {
        int col = h*CHD + nt*8 + 2*tig;
        size_t off0 = ((size_t)b*CS + srow)*CD + col;
        size_t off1 = ((size_t)b*CS + srow + 8)*CD + col;
        __half h0, h1, lo0, lo1;
        split_f16(oacc[nt][0]*inv0, h0, lo0);
        split_f16(oacc[nt][1]*inv0, h1, lo1);
        *(__half2*)(g_Ah + off0) = __halves2half2(h0, h1);
        *(__half2*)(g_Al + off0) = __halves2half2(lo0, lo1);
        split_f16(oacc[nt][2]*inv1, h0, lo0);
        split_f16(oacc[nt][3]*inv1, h1, lo1);
        *(__half2*)(g_Ah + off1) = __halves2half2(h0, h1);
        *(__half2*)(g_Al + off1) = __halves2half2(lo0, lo1);
    }
}

// ---------------- launch -----------------------------------------------------
extern "C" void kernel_launch(void* const* d_in, const int* in_sizes, int n_in,
                              void* d_out, int out_size) {
    const float* hidden = (const float*)d_in[0];
    const int*   posids = (const int*)d_in[1];
    const float* wq = (const float*)d_in[2];
    const float* wk = (const float*)d_in[3];
    const float* wv = (const float*)d_in[4];
    const float* wo = (const float*)d_in[5];
    float* out = (float*)d_out;

    cudaFuncSetAttribute(gemm_tc, cudaFuncAttributeMaxDynamicSharedMemorySize, G_SMEM);
    cudaFuncSetAttribute(attn_tc_kernel, cudaFuncAttributeMaxDynamicSharedMemorySize, AT_SMEM);

    conv_w_kernel<<<dim3(32, 32, 4), dim3(32, 8)>>>(wq, wk, wv, wo);
    conv_split_kernel<<<(CM*CD/4)/256, 256>>>(hidden);
    rope_table_kernel<<<(CS*32 + 255)/256, 256>>>();

    // fused QKV: grid (64, 24), CTA tile 128x128, K-chunk 128
    gemm_tc<<<dim3(CM/128, 24), 512, G_SMEM>>>(1, nullptr);

    rope_apply_kernel<<<(CB*CH*CS*32)/256, 256>>>(posids);
    conv_vt_kernel<<<dim3(CS/32, CHD/32, CB*CH), dim3(32, 8)>>>();

    // attention writes g_Ah/g_Al (fp16 split) directly
    attn_tc_kernel<<<dim3(CNB, CB*CH), 128, AT_SMEM>>>();

    gemm_tc<<<dim3(CM/128, CD/128), 512, G_SMEM>>>(0, out);
}

// round 17
// speedup vs baseline: 1.2990x; 1.2990x over previous
#include <cuda_runtime.h>
#include <cuda_bf16.h>
#include <cuda_fp16.h>
#include <cstdint>
#include <math.h>

#define CB   2
#define CS   4096
#define CD   1024
#define CH   16
#define CHD  64
#define CNB  64
#define CW   8
#define CM   (CB*CS)

// ---------------- scratch (device globals) ----------------------------------
__device__ float g_q[(size_t)CB*CH*CS*CHD];
__device__ float g_k[(size_t)CB*CH*CS*CHD];
__device__ float g_v[(size_t)CB*CH*CS*CHD];
__device__ float g_cos[CS*32];
__device__ float g_sin[CS*32];
__device__ __align__(256) __half g_Ah[(size_t)CM*CD];            // A hi (fp16)
__device__ __align__(256) __half g_Al[(size_t)CM*CD];            // A lo (fp16)
__device__ __align__(256) __half g_W16[(size_t)4*CD*CD];         // W fp16, [n][k]
__device__ __align__(256) __half g_q16[(size_t)CB*CH*CS*CHD];    // (bh,s,hd)
__device__ __align__(256) __half g_k16[(size_t)CB*CH*CS*CHD];    // (bh,s,hd)
__device__ __align__(256) __half g_vt [(size_t)CB*CH*CHD*CS];    // (bh,hd,s)

// ---------------- helpers ----------------------------------------------------
__device__ __forceinline__ uint32_t smem_u32(const void* p) {
    uint32_t a;
    asm("{ .reg .u64 t; cvta.to.shared.u64 t, %1; cvt.u32.u64 %0, t; }" : "=r"(a) : "l"(p));
    return a;
}
#define SWZ(o) ((o) ^ (((o) >> 3) & 0x70))

#define CP16(d, s) \
    asm volatile("cp.async.cg.shared.global [%0], [%1], 16;" :: "r"((uint32_t)(d)), "l"(s) : "memory")

__device__ __forceinline__ void ldsm4(uint32_t* r, uint32_t addr) {
    asm volatile("ldmatrix.sync.aligned.m8n8.x4.shared.b16 {%0,%1,%2,%3}, [%4];"
        : "=r"(r[0]), "=r"(r[1]), "=r"(r[2]), "=r"(r[3]) : "r"(addr));
}

__device__ __forceinline__ void mma_f16(float* c, const uint32_t* a, uint32_t b0, uint32_t b1) {
    asm volatile("mma.sync.aligned.m16n8k16.row.col.f32.f16.f16.f32 "
        "{%0,%1,%2,%3}, {%4,%5,%6,%7}, {%8,%9}, {%0,%1,%2,%3};"
        : "+f"(c[0]), "+f"(c[1]), "+f"(c[2]), "+f"(c[3])
        : "r"(a[0]), "r"(a[1]), "r"(a[2]), "r"(a[3]), "r"(b0), "r"(b1));
}

// exp2 without MUFU: magic-number round + deg-5 poly + exponent splice.
__device__ __forceinline__ float exp2p(float y) {
    y = fmaxf(y, -126.0f);
    float t = y + 12582912.0f;
    int   n = __float_as_int(t) - 0x4B400000;
    float f = y - (t - 12582912.0f);
    float p = 0.0013333558f;
    p = fmaf(p, f, 0.0096181291f);
    p = fmaf(p, f, 0.0555041087f);
    p = fmaf(p, f, 0.2402265069f);
    p = fmaf(p, f, 0.6931471806f);
    p = fmaf(p, f, 1.0f);
    return p * __int_as_float((n + 127) << 23);
}

__device__ __forceinline__ uint32_t pack_h2(float a, float b) {
    __half2 h = __floats2half2_rn(a, b);
    return *reinterpret_cast<uint32_t*>(&h);
}

// fp16 hi/lo split of one fp32 (A near-exact: residual ~2^-24)
__device__ __forceinline__ void split_f16(float x, __half& h, __half& l) {
    h = __float2half(x);
    l = __float2half(x - __half2float(h));
}

// ---------------- RoPE tables ------------------------------------------------
__global__ void rope_table_kernel() {
    int idx = blockIdx.x * blockDim.x + threadIdx.x;
    if (idx >= CS*32) return;
    int p = idx >> 5;
    int j = idx & 31;
    double expo = (double)(2*j) / 64.0;
    double freq = exp(-expo * log(10000.0));
    double ang  = (double)p * freq;
    g_cos[idx] = (float)cos(ang);
    g_sin[idx] = (float)sin(ang);
}

__global__ void rope_apply_kernel(const int* __restrict__ posids) {
    int idx = blockIdx.x * blockDim.x + threadIdx.x;
    int j  = idx & 31;
    int s  = (idx >> 5) & (CS - 1);
    int bh = idx >> 17;
    int b  = bh >> 4;
    int p  = posids[b*CS + s];
    float c  = g_cos[p*32 + j];
    float sn = g_sin[p*32 + j];
    size_t base = ((size_t)bh*CS + (size_t)s)*CHD + j;
    float q1 = g_q[base], q2 = g_q[base+32];
    g_q16[base]    = __float2half(q1*c - q2*sn);
    g_q16[base+32] = __float2half(q2*c + q1*sn);
    float k1 = g_k[base], k2 = g_k[base+32];
    g_k16[base]    = __float2half(k1*c - k2*sn);
    g_k16[base+32] = __float2half(k2*c + k1*sn);
}

// V: fp32 (bh,s,hd) -> fp16 transposed (bh,hd,s)
__global__ void conv_vt_kernel() {
    __shared__ float t[32][33];
    int bh = blockIdx.z;
    int s0 = blockIdx.x * 32;
    int h0 = blockIdx.y * 32;
    int tx = threadIdx.x, ty = threadIdx.y;   // 32 x 8
#pragma unroll
    for (int r = 0; r < 4; r++)
        t[ty + 8*r][tx] = g_v[((size_t)bh*CS + s0 + ty + 8*r)*CHD + h0 + tx];
    __syncthreads();
#pragma unroll
    for (int r = 0; r < 4; r++)
        g_vt[((size_t)bh*CHD + h0 + ty + 8*r)*CS + s0 + tx] = __float2half(t[tx][ty + 8*r]);
}

// ---------------- fp32 -> fp16 (row-major A, hi only: QKV is 1-product) ------
__global__ void conv_split_kernel(const float* __restrict__ src) {
    int i = blockIdx.x * blockDim.x + threadIdx.x;
    size_t base = (size_t)i * 4;
    float4 v = *(const float4*)(src + base);
    *(__half2*)(g_Ah + base)     = __floats2half2_rn(v.x, v.y);
    *(__half2*)(g_Ah + base + 2) = __floats2half2_rn(v.z, v.w);
}

// ---------------- weights: fp32 [k][n] -> fp16 transposed [n][k] -------------
__global__ void conv_w_kernel(const float* __restrict__ w0, const float* __restrict__ w1,
                              const float* __restrict__ w2, const float* __restrict__ w3) {
    __shared__ float t[32][33];
    int wz = blockIdx.z;
    const float* W = (wz == 0) ? w0 : (wz == 1) ? w1 : (wz == 2) ? w2 : w3;
    int n0 = blockIdx.x * 32, k0 = blockIdx.y * 32;
    int tx = threadIdx.x, ty = threadIdx.y;   // 32 x 8
#pragma unroll
    for (int r = 0; r < 4; r++) {
        int k = ty + r*8;
        t[k][tx] = W[(size_t)(k0 + k)*CD + n0 + tx];
    }
    __syncthreads();
    size_t off = (size_t)wz * CD * CD;
#pragma unroll
    for (int r = 0; r < 4; r++) {
        int nn = ty + r*8;
        g_W16[off + (size_t)(n0 + nn)*CD + k0 + tx] = __float2half(t[tx][nn]);
    }
}

// ---------------- split-fp16 GEMM via mma.sync (m16n8k16) --------------------
// lo=0: C = Ah @ B16 (QKV; q/k/v are fp16-rounded downstream anyway)
// lo=1: C = (Ah + Al) @ B16 (output projection; full accuracy)
// CTA 128x128, 512 thr, 16 warps (4m x 4n), warp tile 32x32.
#define G_TILE    16384
#define G_STAGE   (3*G_TILE)
#define G_SMEM    (1024 + 2*G_STAGE)       /* 99328 */

__device__ __forceinline__ void g_load_stage(uint32_t dat, int s, int m0, int n0, int tid,
                                             const __half* Bw, int lo) {
    uint32_t buf = dat + (uint32_t)(s & 1) * G_STAGE;
    int k0 = s * 64;
#pragma unroll
    for (int i = 0; i < 2; i++) {
        int cc  = tid + 512*i;
        int row = cc >> 3;
        int kc  = cc & 7;
        uint32_t d = SWZ(row*128 + kc*16);
        size_t ea = (size_t)(m0 + row)*CD + k0 + kc*8;
        size_t eb = (size_t)(n0 + row)*CD + k0 + kc*8;
        CP16(buf + d,             g_Ah + ea);
        if (lo) CP16(buf + G_TILE + d, g_Al + ea);
        CP16(buf + 2*G_TILE + d,  Bw + eb);
    }
    asm volatile("cp.async.commit_group;" ::: "memory");
}

__global__ __launch_bounds__(512) void gemm_tc(int fused, float* __restrict__ outp) {
    extern __shared__ char smem_raw[];
    uint32_t sb_raw = smem_u32(smem_raw);
    uint32_t dat = (sb_raw + 1023u) & ~1023u;

    const int tid  = threadIdx.x;
    const int wid  = tid >> 5, lane = tid & 31;
    const int wm   = wid >> 2;
    const int wn   = wid & 3;
    const int m0   = blockIdx.x * 128;
    const int widx = fused ? (int)(blockIdx.y >> 3) : 3;
    const int n0   = fused ? (int)(blockIdx.y & 7) * 128 : (int)blockIdx.y * 128;
    const int mode = fused ? widx : 3;
    const int lo   = fused ? 0 : 1;

    const __half* Bw = g_W16 + ((size_t)widx << 20);

    float acc[2][4][4];
#pragma unroll
    for (int mt = 0; mt < 2; mt++)
#pragma unroll
        for (int nt = 0; nt < 4; nt++)
#pragma unroll
            for (int e = 0; e < 4; e++) acc[mt][nt][e] = 0.f;

    const int g  = lane >> 3, r = lane & 7;
    const int arow = wm*32 + (g & 1)*8 + r;
    const int brow = wn*32 + (g & 1)*8 + r;
    const int kcol = (g >> 1) * 16;

    g_load_stage(dat, 0, m0, n0, tid, Bw, lo);

    for (int s = 0; s < 16; s++) {
        if (s + 1 < 16) {
            g_load_stage(dat, s + 1, m0, n0, tid, Bw, lo);
            asm volatile("cp.async.wait_group 1;" ::: "memory");
        } else {
            asm volatile("cp.async.wait_group 0;" ::: "memory");
        }
        __syncthreads();

        uint32_t buf = dat + (uint32_t)(s & 1) * G_STAGE;
        uint32_t tAh = buf, tAl = buf + G_TILE, tB = buf + 2*G_TILE;

#pragma unroll
        for (int ks = 0; ks < 4; ks++) {
            const int kb = ks*32 + kcol;
            uint32_t ah[2][4], bx[2][4];
#pragma unroll
            for (int mt = 0; mt < 2; mt++)
                ldsm4(ah[mt], tAh + SWZ((arow + mt*16)*128 + kb));
#pragma unroll
            for (int ng = 0; ng < 2; ng++)
                ldsm4(bx[ng], tB + SWZ((brow + ng*16)*128 + kb));
#pragma unroll
            for (int mt = 0; mt < 2; mt++)
#pragma unroll
                for (int nt = 0; nt < 4; nt++)
                    mma_f16(acc[mt][nt], ah[mt], bx[nt>>1][nt&1], bx[nt>>1][(nt&1)+2]);
            if (lo) {
                uint32_t al[2][4];
#pragma unroll
                for (int mt = 0; mt < 2; mt++)
                    ldsm4(al[mt], tAl + SWZ((arow + mt*16)*128 + kb));
#pragma unroll
                for (int mt = 0; mt < 2; mt++)
#pragma unroll
                    for (int nt = 0; nt < 4; nt++)
                        mma_f16(acc[mt][nt], al[mt], bx[nt>>1][nt&1], bx[nt>>1][(nt&1)+2]);
            }
        }
        __syncthreads();
    }

    // epilogue
    const int gid = lane >> 2, tig = lane & 3;
    const int b_ = m0 >> 12;
    float* dst = (mode == 0) ? g_q : (mode == 1) ? g_k : g_v;
#pragma unroll
    for (int mt = 0; mt < 2; mt++) {
#pragma unroll
        for (int nt = 0; nt < 4; nt++) {
            int mrow = m0 + wm*32 + mt*16 + gid;
            int ncol = n0 + wn*32 + nt*8 + tig*2;
#pragma unroll
            for (int half = 0; half < 2; half++) {
                int m = mrow + half*8;
                float2 val = make_float2(acc[mt][nt][half*2], acc[mt][nt][half*2 + 1]);
                if (mode == 3) {
                    *(float2*)(outp + (size_t)m*CD + ncol) = val;
                } else {
                    int h  = ncol >> 6, hd = ncol & 63;
                    int s_ = m & (CS - 1);
                    *(float2*)(dst + (((size_t)(b_*CH + h))*CS + s_)*CHD + hd) = val;
                }
            }
        }
    }
}

// ---------------- fp16 tensor-core flash attention ---------------------------
// epilogue writes fp16 hi/lo A-operand for the output projection directly.
#define AT_TILE   8192
#define AT_SMEM   (1024 + 5*AT_TILE)

__device__ __forceinline__ void at_stage(uint32_t kbuf, const __half* ksrc,
                                         const __half* vtsrc, int tid) {
#pragma unroll
    for (int i = 0; i < 4; i++) {
        int cc  = tid + 128*i;
        int row = cc >> 3;
        int kc  = cc & 7;
        uint32_t d = SWZ(row*128 + kc*16);
        CP16(kbuf + d,           ksrc  + (size_t)row*CHD + kc*8);
        CP16(kbuf + AT_TILE + d, vtsrc + (size_t)row*CS  + kc*8);
    }
    asm volatile("cp.async.commit_group;" ::: "memory");
}

__global__ __launch_bounds__(128) void attn_tc_kernel() {
    extern __shared__ char sraw[];
    uint32_t dat = (smem_u32(sraw) + 1023u) & ~1023u;

    const int n   = blockIdx.x;
    const int bh  = blockIdx.y;
    const int tid = threadIdx.x;
    const int w   = tid >> 5, lane = tid & 31;
    const int g   = lane >> 3, r = lane & 7;
    const int gid = lane >> 2, tig = lane & 3;

    const __half* qsrc = g_q16 + ((size_t)bh*CS + (size_t)n*64)*CHD;
#pragma unroll
    for (int i = 0; i < 4; i++) {
        int cc = tid + 128*i;
        int row = cc >> 3;
        int kc  = cc & 7;
        CP16(dat + SWZ(row*128 + kc*16), qsrc + (size_t)row*CHD + kc*8);
    }
    asm volatile("cp.async.commit_group;" ::: "memory");

    const int kb0 = (n - (CW-1) < 0) ? 0 : n - (CW-1);
    const int nk  = n - kb0 + 1;
    const __half* kbase_g  = g_k16 + ((size_t)bh*CS)*CHD;
    const __half* vtbase_g = g_vt  + ((size_t)bh*CHD)*CS;

    at_stage(dat + AT_TILE, kbase_g + (size_t)kb0*64*CHD, vtbase_g + kb0*64, tid);

    float oacc[8][4];
#pragma unroll
    for (int nt = 0; nt < 8; nt++)
#pragma unroll
        for (int e = 0; e < 4; e++) oacc[nt][e] = 0.f;
    float m0 = -1e30f, m1 = -1e30f, l0 = 0.f, l1 = 0.f;
    uint32_t qf[4][4];

    const float SCL = 0.18033688011f;    // 0.125 * log2(e)
    const int ql0 = w*16 + gid, ql1 = ql0 + 8;

    for (int i = 0; i < nk; i++) {
        const int kb = kb0 + i;
        asm volatile("cp.async.wait_group 0;" ::: "memory");
        __syncthreads();

        if (i == 0) {
#pragma unroll
            for (int kc = 0; kc < 4; kc++)
                ldsm4(qf[kc], dat + SWZ((w*16 + (g&1)*8 + r)*128 + (g>>1)*16 + kc*32));
        }
        if (i + 1 < nk)
            at_stage(dat + AT_TILE + ((i+1)&1)*2*AT_TILE,
                     kbase_g + (size_t)(kb+1)*64*CHD, vtbase_g + (kb+1)*64, tid);

        const uint32_t kbuf = dat + AT_TILE + (i&1)*2*AT_TILE;
        const uint32_t vbuf = kbuf + AT_TILE;

        float sacc[8][4];
#pragma unroll
        for (int nt = 0; nt < 8; nt++)
#pragma unroll
            for (int e = 0; e < 4; e++) sacc[nt][e] = 0.f;

#pragma unroll
        for (int kc = 0; kc < 4; kc++) {
            uint32_t kf[4][4];
#pragma unroll
            for (int ng = 0; ng < 4; ng++)
                ldsm4(kf[ng], kbuf + SWZ((ng*16 + (g&1)*8 + r)*128 + (g>>1)*16 + kc*32));
#pragma unroll
            for (int nt = 0; nt < 8; nt++)
                mma_f16(sacc[nt], qf[kc], kf[nt>>1][nt&1], kf[nt>>1][(nt&1)+2]);
        }

#pragma unroll
        for (int nt = 0; nt < 8; nt++)
#pragma unroll
            for (int e = 0; e < 4; e++) sacc[nt][e] *= SCL;
        if (kb == n) {
#pragma unroll
            for (int nt = 0; nt < 8; nt++) {
                int c0 = nt*8 + 2*tig, c1 = c0 + 1;
                if (c0 > ql0) sacc[nt][0] = -1e30f;
                if (c1 > ql0) sacc[nt][1] = -1e30f;
                if (c0 > ql1) sacc[nt][2] = -1e30f;
                if (c1 > ql1) sacc[nt][3] = -1e30f;
            }
        }

        float mx0 = -1e30f, mx1 = -1e30f;
#pragma unroll
        for (int nt = 0; nt < 8; nt++) {
            mx0 = fmaxf(mx0, fmaxf(sacc[nt][0], sacc[nt][1]));
            mx1 = fmaxf(mx1, fmaxf(sacc[nt][2], sacc[nt][3]));
        }
        mx0 = fmaxf(mx0, __shfl_xor_sync(0xffffffffu, mx0, 1));
        mx0 = fmaxf(mx0, __shfl_xor_sync(0xffffffffu, mx0, 2));
        mx1 = fmaxf(mx1, __shfl_xor_sync(0xffffffffu, mx1, 1));
        mx1 = fmaxf(mx1, __shfl_xor_sync(0xffffffffu, mx1, 2));
        float mn0 = fmaxf(m0, mx0), mn1 = fmaxf(m1, mx1);
        float cr0 = exp2p(m0 - mn0), cr1 = exp2p(m1 - mn1);
        m0 = mn0; m1 = mn1;
        float rs0 = 0.f, rs1 = 0.f;
#pragma unroll
        for (int nt = 0; nt < 8; nt++) {
            sacc[nt][0] = exp2p(sacc[nt][0] - mn0);
            sacc[nt][1] = exp2p(sacc[nt][1] - mn0);
            sacc[nt][2] = exp2p(sacc[nt][2] - mn1);
            sacc[nt][3] = exp2p(sacc[nt][3] - mn1);
            rs0 += sacc[nt][0] + sacc[nt][1];
            rs1 += sacc[nt][2] + sacc[nt][3];
        }
        rs0 += __shfl_xor_sync(0xffffffffu, rs0, 1);
        rs0 += __shfl_xor_sync(0xffffffffu, rs0, 2);
        rs1 += __shfl_xor_sync(0xffffffffu, rs1, 1);
        rs1 += __shfl_xor_sync(0xffffffffu, rs1, 2);
        l0 = l0*cr0 + rs0;
        l1 = l1*cr1 + rs1;
#pragma unroll
        for (int nt = 0; nt < 8; nt++) {
            oacc[nt][0] *= cr0; oacc[nt][1] *= cr0;
            oacc[nt][2] *= cr1; oacc[nt][3] *= cr1;
        }

#pragma unroll
        for (int kc = 0; kc < 4; kc++) {
            uint32_t pf[4];
            pf[0] = pack_h2(sacc[2*kc][0],   sacc[2*kc][1]);
            pf[1] = pack_h2(sacc[2*kc][2],   sacc[2*kc][3]);
            pf[2] = pack_h2(sacc[2*kc+1][0], sacc[2*kc+1][1]);
            pf[3] = pack_h2(sacc[2*kc+1][2], sacc[2*kc+1][3]);
            uint32_t vf[4][4];
#pragma unroll
            for (int ng = 0; ng < 4; ng++)
                ldsm4(vf[ng], vbuf + SWZ((ng*16 + (g&1)*8 + r)*128 + (g>>1)*16 + kc*32));
#pragma unroll
            for (int nt = 0; nt < 8; nt++)
                mma_f16(oacc[nt], pf, vf[nt>>1][nt&1], vf[nt>>1][(nt&1)+2]);
        }
        __syncthreads();
    }

    // ---- epilogue: normalize, split to fp16 hi/lo into g_Ah/g_Al ------------
    const float inv0 = 1.0f / l0, inv1 = 1.0f / l1;
    const int b = bh >> 4, h = bh & 15;
    const int srow = n*64 + w*16 + gid;
#pragma unroll
    for (int nt = 0; nt < 8; nt++) {
        int col = h*CHD + nt*8 + 2*tig;
        size_t off0 = ((size_t)b*CS + srow)*CD + col;
        size_t off1 = ((size_t)b*CS + srow + 8)*CD + col;
        __half h0, h1, lo0, lo1;
        split_f16(oacc[nt][0]*inv0, h0, lo0);
        split_f16(oacc[nt][1]*inv0, h1, lo1);
        *(__half2*)(g_Ah + off0) = __halves2half2(h0, h1);
        *(__half2*)(g_Al + off0) = __halves2half2(lo0, lo1);
        split_f16(oacc[nt][2]*inv1, h0, lo0);
        split_f16(oacc[nt][3]*inv1, h1, lo1);
        *(__half2*)(g_Ah + off1) = __halves2half2(h0, h1);
        *(__half2*)(g_Al + off1) = __halves2half2(lo0, lo1);
    }
}

// ---------------- launch -----------------------------------------------------
extern "C" void kernel_launch(void* const* d_in, const int* in_sizes, int n_in,
                              void* d_out, int out_size) {
    const float* hidden = (const float*)d_in[0];
    const int*   posids = (const int*)d_in[1];
    const float* wq = (const float*)d_in[2];
    const float* wk = (const float*)d_in[3];
    const float* wv = (const float*)d_in[4];
    const float* wo = (const float*)d_in[5];
    float* out = (float*)d_out;

    cudaFuncSetAttribute(gemm_tc, cudaFuncAttributeMaxDynamicSharedMemorySize, G_SMEM);
    cudaFuncSetAttribute(attn_tc_kernel, cudaFuncAttributeMaxDynamicSharedMemorySize, AT_SMEM);

    conv_w_kernel<<<dim3(32, 32, 4), dim3(32, 8)>>>(wq, wk, wv, wo);
    conv_split_kernel<<<(CM*CD/4)/256, 256>>>(hidden);
    rope_table_kernel<<<(CS*32 + 255)/256, 256>>>();

    // fused QKV: grid (64, 24), 1-product (Ah only)
    gemm_tc<<<dim3(CM/128, 24), 512, G_SMEM>>>(1, nullptr);

    rope_apply_kernel<<<(CB*CH*CS*32)/256, 256>>>(posids);
    conv_vt_kernel<<<dim3(CS/32, CHD/32, CB*CH), dim3(32, 8)>>>();

    // attention writes g_Ah/g_Al (fp16 split) directly
    attn_tc_kernel<<<dim3(CNB, CB*CH), 128, AT_SMEM>>>();

    // output projection: 2-product (Ah + Al)
    gemm_tc<<<dim3(CM/128, CD/128), 512, G_SMEM>>>(0, out);
}